// round 10
// baseline (speedup 1.0000x reference)
#include <cuda_runtime.h>

// NLSearch: vid0, vid1 (1,3,32,256,256) f32. Query grid 64x64 stride 4,
// patch 7x7, shift window 8x8 (offsets -4..3), K=7.
// 256 thr / 8 warps. Warp w = (pair p=w&3, half h=w>>2): shift rows 2p,2p+1
// over patch rows i in [0,3] or [4,6]; b rows streamed once, a-row carried.
// Output float32: [0,86016) dists (1,1,12288,7); [86016,344064) inds (..,7,3).

#define V1_CSTR 197   // 14*14=196 padded to 197 (odd -> conflict-free)
#define V0_CSTR 49    // 7*7 = 49 (odd -> conflict-free)

__device__ __forceinline__ int refl(int x) {
    x = x < 0 ? -x : x;
    return x > 255 ? 510 - x : x;
}

// Stream b rows r = ILO .. IHI+1 (offset from shift row 2p).
// acc0 (shift 2p):   i = r   in [ILO, IHI]
// acc1 (shift 2p+1): i = r-1 in [ILO, IHI]  (a-row carried from prev step)
template <int ILO, int IHI>
__device__ __forceinline__ void compute_half(
    const float* __restrict__ a_base,
    const float* __restrict__ b_base,
    float* __restrict__ acc0,
    float* __restrict__ acc1)
{
    float aPrev[7];
#pragma unroll
    for (int r = ILO; r <= IHI + 1; r++) {
        float bb[14];
        const float* br = b_base + r * 14;
#pragma unroll
        for (int j = 0; j < 14; j++) bb[j] = br[j];

        if (r <= IHI) {
            float aCur[7];
            const float* ar = a_base + r * 7;
#pragma unroll
            for (int j = 0; j < 7; j++) aCur[j] = ar[j];
#pragma unroll
            for (int s = 0; s < 8; s++)
#pragma unroll
                for (int j = 0; j < 7; j++)
                    acc0[s] = fmaf(aCur[j], bb[j + s], acc0[s]);
            if (r >= ILO + 1) {
#pragma unroll
                for (int s = 0; s < 8; s++)
#pragma unroll
                    for (int j = 0; j < 7; j++)
                        acc1[s] = fmaf(aPrev[j], bb[j + s], acc1[s]);
            }
#pragma unroll
            for (int j = 0; j < 7; j++) aPrev[j] = aCur[j];
        } else {
            // last row: only acc1 (i = IHI)
#pragma unroll
            for (int s = 0; s < 8; s++)
#pragma unroll
                for (int j = 0; j < 7; j++)
                    acc1[s] = fmaf(aPrev[j], bb[j + s], acc1[s]);
        }
    }
}

__global__ void __launch_bounds__(256, 5)
nls_kernel(const float* __restrict__ vid0,
           const float* __restrict__ vid1,
           float* __restrict__ out)
{
    __shared__ float v1s[32 * V1_CSTR]; // [c][rr*14+cc], rows qh-7..qh+6
    __shared__ float v0s[32 * V0_CSTR]; // [c][ii*7+jj],  rows qh-3..qh+3
    __shared__ float sd2[2][64];        // per-half partial dists

    const int b = blockIdx.x;
    const int t = b >> 12;
    const int r = b & 4095;
    const int n = r >> 6;
    const int v = r & 63;
    const int qh = n << 2;
    const int qw = v << 2;

    const int tid  = threadIdx.x;
    const int lane = tid & 31;
    const int w    = tid >> 5;
    const int p    = w & 3;          // shift-row pair: rows 2p, 2p+1
    const int h    = w >> 2;         // patch-row half: 0 -> i 0..3, 1 -> i 4..6

    // ---- stage: thread->(element) fixed once, loop channels ----
    if (tid < 196) {
        int rr = tid / 14;
        int cc = tid - rr * 14;
        int hg = refl(qh - 7 + rr);
        int wg = refl(qw - 7 + cc);
        const float* src = vid1 + (size_t)t * 32 * 65536 + (hg << 8) + wg;
        float* dst = v1s + tid;
#pragma unroll 8
        for (int c = 0; c < 32; c++)
            dst[c * V1_CSTR] = src[c << 16];
    } else if (tid < 196 + 49) {
        int idx = tid - 196;
        int ii = idx / 7;
        int jj = idx - ii * 7;
        int hg = refl(qh - 3 + ii);
        int wg = refl(qw - 3 + jj);
        const float* src = vid0 + (size_t)t * 32 * 65536 + (hg << 8) + wg;
        float* dst = v0s + idx;
#pragma unroll 8
        for (int c = 0; c < 32; c++)
            dst[c * V0_CSTR] = src[c << 16];
    }
    __syncthreads();

    // ---- compute: lane = channel; b rows offset from shift row 2p ----
    const float* a_base = v0s + lane * V0_CSTR;
    const float* b_base = v1s + lane * V1_CSTR + (2 * p) * 14;

    float acc0[8], acc1[8];
#pragma unroll
    for (int s = 0; s < 8; s++) { acc0[s] = 0.f; acc1[s] = 0.f; }

    if (h == 0) compute_half<0, 3>(a_base, b_base, acc0, acc1);
    else        compute_half<4, 6>(a_base, b_base, acc0, acc1);

    // ---- warp-reduce 16 partials over channels; lane0 stores ----
#pragma unroll
    for (int s = 0; s < 8; s++) {
        float v0r = acc0[s];
        float v1r = acc1[s];
#pragma unroll
        for (int o = 16; o > 0; o >>= 1) {
            v0r += __shfl_xor_sync(0xffffffffu, v0r, o);
            v1r += __shfl_xor_sync(0xffffffffu, v1r, o);
        }
        if (lane == 0) {
            sd2[h][16 * p + s]     = v0r;   // shift row 2p,   col s
            sd2[h][16 * p + 8 + s] = v1r;   // shift row 2p+1, col s
        }
    }
    __syncthreads();

    // ---- top-7 (warp 0): combine halves, then value desc / index asc ----
    if (w == 0) {
        float c0 = sd2[0][lane]      + sd2[1][lane];
        float c1 = sd2[0][lane + 32] + sd2[1][lane + 32];
        sd2[0][lane]      = c0;   // combined values for winner lookup
        sd2[0][lane + 32] = c1;
        __syncwarp();

        float a0 = c0;
        float a1 = (lane == 4) ? c1 + 1e30f : c1;  // self shift idx 36 boost

        const int q = t * 4096 + n * 64 + v;
        float* dbase = out + (size_t)q * 7;
        float* ibase = out + 86016 + (size_t)q * 21;

#pragma unroll
        for (int k = 0; k < 7; k++) {
            float bv = (a0 >= a1) ? a0 : a1;
            int   bi = (a0 >= a1) ? lane : lane + 32;
#pragma unroll
            for (int o = 16; o > 0; o >>= 1) {
                float ov = __shfl_xor_sync(0xffffffffu, bv, o);
                int   oi = __shfl_xor_sync(0xffffffffu, bi, o);
                if (ov > bv || (ov == bv && oi < bi)) { bv = ov; bi = oi; }
            }
            if (bi == lane)      a0 = -3.4e38f;
            if (bi == lane + 32) a1 = -3.4e38f;
            if (lane == 0) {
                dbase[k] = sd2[0][bi];
                int s0 = bi >> 3;
                int s1 = bi & 7;
                ibase[k * 3 + 0] = (float)t;
                ibase[k * 3 + 1] = (float)refl(qh + s0 - 4);
                ibase[k * 3 + 2] = (float)refl(qw + s1 - 4);
            }
        }
    }
}

extern "C" void kernel_launch(void* const* d_in, const int* in_sizes, int n_in,
                              void* d_out, int out_size)
{
    const float* vid0 = (const float*)d_in[0];
    const float* vid1 = (const float*)d_in[1];
    float* out = (float*)d_out;
    nls_kernel<<<12288, 256>>>(vid0, vid1, out);
}

// round 11
// speedup vs baseline: 1.1358x; 1.1358x over previous
#include <cuda_runtime.h>

// NLSearch: vid0, vid1 (1,3,32,256,256) f32. Query grid 64x64 stride 4,
// patch 7x7, shift window 8x8 (offsets -4..3), K=7.
// R8 skeleton (champion): 256 thr, warp = shift row, lane = channel, occ 6.
// This round: LDS.64 loads via 8B-aligned conflict-free strides (zero new regs).
// Output float32: [0,86016) dists (1,1,12288,7); [86016,344064) inds (..,7,3).

#define V1_CSTR 198   // 14*14=196 -> 198: even (8B align), 6*dl % 32 != 0 in phase -> CF
#define V0_RSTR 8     // v0 rows padded 7 -> 8 (keeps every row 8B aligned)
#define V0_CSTR 58    // 7*8=56 -> 58: even, 26*dl % 32 != 0 in phase -> CF

__device__ __forceinline__ int refl(int x) {
    x = x < 0 ? -x : x;
    return x > 255 ? 510 - x : x;
}

__global__ void __launch_bounds__(256, 6)
nls_kernel(const float* __restrict__ vid0,
           const float* __restrict__ vid1,
           float* __restrict__ out)
{
    __shared__ __align__(16) float v1s[32 * V1_CSTR]; // [c][rr*14+cc], rows qh-7..qh+6
    __shared__ __align__(16) float v0s[32 * V0_CSTR]; // [c][ii*8+jj],  rows qh-3..qh+3
    __shared__ float sdist[64];

    const int b = blockIdx.x;
    const int t = b >> 12;
    const int r = b & 4095;
    const int n = r >> 6;
    const int v = r & 63;
    const int qh = n << 2;
    const int qw = v << 2;

    const int tid  = threadIdx.x;
    const int lane = tid & 31;
    const int w    = tid >> 5;       // warp id = s0 index (s0 = w - 4)

    // ---- stage: thread->(element) fixed once, loop channels ----
    if (tid < 196) {
        int rr = tid / 14;
        int cc = tid - rr * 14;
        int hg = refl(qh - 7 + rr);
        int wg = refl(qw - 7 + cc);
        const float* src = vid1 + (size_t)t * 32 * 65536 + (hg << 8) + wg;
        float* dst = v1s + rr * 14 + cc;
#pragma unroll 8
        for (int c = 0; c < 32; c++) {
            dst[c * V1_CSTR] = src[c << 16];
        }
    } else if (tid < 196 + 49) {
        int idx = tid - 196;
        int ii = idx / 7;
        int jj = idx - ii * 7;
        int hg = refl(qh - 3 + ii);
        int wg = refl(qw - 3 + jj);
        const float* src = vid0 + (size_t)t * 32 * 65536 + (hg << 8) + wg;
        float* dst = v0s + ii * V0_RSTR + jj;
#pragma unroll 8
        for (int c = 0; c < 32; c++) {
            dst[c * V0_CSTR] = src[c << 16];
        }
    }
    __syncthreads();

    // ---- compute: warp w = shift row s0; lane = channel c; loop i = patch row.
    // acc[s1] += v0[c][i][j] * v1[c][w+i][j+s1]; LDS.64 loads, scalar FFMA.
    const float* a_base = v0s + lane * V0_CSTR;        // 232B*lane -> 8B aligned
    const float* b_base = v1s + lane * V1_CSTR + w * 14; // 792B*lane + 56B*w -> 8B aligned

    float acc[8];
#pragma unroll
    for (int s = 0; s < 8; s++) acc[s] = 0.f;

#pragma unroll
    for (int i = 0; i < 7; i++) {
        const float2* ar = (const float2*)(a_base + i * V0_RSTR);
        const float2* br = (const float2*)(b_base + i * 14);
        float2 A0 = ar[0], A1 = ar[1], A2 = ar[2], A3 = ar[3];
        float2 B0 = br[0], B1 = br[1], B2 = br[2], B3 = br[3],
               B4 = br[4], B5 = br[5], B6 = br[6];

        float a[7]  = {A0.x, A0.y, A1.x, A1.y, A2.x, A2.y, A3.x};
        float bb[14] = {B0.x, B0.y, B1.x, B1.y, B2.x, B2.y, B3.x, B3.y,
                        B4.x, B4.y, B5.x, B5.y, B6.x, B6.y};

#pragma unroll
        for (int s = 0; s < 8; s++)
#pragma unroll
            for (int j = 0; j < 7; j++)
                acc[s] = fmaf(a[j], bb[j + s], acc[s]);
    }

    // ---- warp-reduce 8 partials (sum over channels) ----
#pragma unroll
    for (int s = 0; s < 8; s++) {
        float val = acc[s];
#pragma unroll
        for (int o = 16; o > 0; o >>= 1)
            val += __shfl_xor_sync(0xffffffffu, val, o);
        if (lane == 0) sdist[(w << 3) + s] = val;
    }
    __syncthreads();

    // ---- top-7 (warp 0): value desc, index asc tie-break ----
    if (w == 0) {
        float a0 = sdist[lane];
        float a1 = sdist[lane + 32];
        if (lane == 4) a1 += 1e30f;   // self shift idx 36 boosted for selection

        const int q = t * 4096 + n * 64 + v;
        float* dbase = out + (size_t)q * 7;
        float* ibase = out + 86016 + (size_t)q * 21;

#pragma unroll
        for (int k = 0; k < 7; k++) {
            float bv = (a0 >= a1) ? a0 : a1;
            int   bi = (a0 >= a1) ? lane : lane + 32;
#pragma unroll
            for (int o = 16; o > 0; o >>= 1) {
                float ov = __shfl_xor_sync(0xffffffffu, bv, o);
                int   oi = __shfl_xor_sync(0xffffffffu, bi, o);
                if (ov > bv || (ov == bv && oi < bi)) { bv = ov; bi = oi; }
            }
            if (bi == lane)      a0 = -3.4e38f;
            if (bi == lane + 32) a1 = -3.4e38f;
            if (lane == 0) {
                dbase[k] = sdist[bi];
                int s0 = bi >> 3;
                int s1 = bi & 7;
                ibase[k * 3 + 0] = (float)t;
                ibase[k * 3 + 1] = (float)refl(qh + s0 - 4);
                ibase[k * 3 + 2] = (float)refl(qw + s1 - 4);
            }
        }
    }
}

extern "C" void kernel_launch(void* const* d_in, const int* in_sizes, int n_in,
                              void* d_out, int out_size)
{
    const float* vid0 = (const float*)d_in[0];
    const float* vid1 = (const float*)d_in[1];
    float* out = (float*)d_out;
    nls_kernel<<<12288, 256>>>(vid0, vid1, out);
}

// round 12
// speedup vs baseline: 1.8312x; 1.6122x over previous
#include <cuda_runtime.h>

// NLSearch via column factorization.
// dists[n,m][s0,s1] = sum_j colP[4m-3+j][s0-4][s1-4], where
// colP[x][dy][dx] = sum_{c,i} v0[c][refl(4n-3+i)][refl(x)] *
//                            v1[c][refl(4n-3+i+dy)][refl(x+dx)]
// CTA = (t, n, half-row h0): queries m in [32*h0, 32*h0+32).
// 288 threads: thread (xi = tid>>1 in [0,131), dh = tid&1) owns
// colP[x0+xi][dy in 4*dh..4*dh+3][dx 0..8) -> 32 register accumulators.
// Channels streamed in chunks of 4 through smem.
// Output float32: [0,86016) dists (1,1,12288,7); [86016,344064) inds (..,7,3).

#define THREADS 288
#define NX      131            // colP columns per CTA (4*31+7)
#define V0_RS   131            // v0s row stride
#define V0_CS   917            // 7*131 channel stride
#define V1_W    138            // staged v1 cols
#define V1_RS   140            // padded row stride: 4*140 = 560 = 16 mod 32 -> dh halves on disjoint banks
#define V1_CS   1960           // 14*140
#define COLP_S  65             // colP[x*65 + s]

__device__ __forceinline__ int refl(int x) {
    x = x < 0 ? -x : x;
    return x > 255 ? 510 - x : x;
}

__global__ void __launch_bounds__(THREADS, 3)
nls_kernel(const float* __restrict__ vid0,
           const float* __restrict__ vid1,
           float* __restrict__ out)
{
    // union buffer: phase A: v0s [0,3668) + v1s [3668, 3668+7837]
    //               phase B: colP [0, 8515) + dists [8515, 10563)
    __shared__ float buf[11552];
    float* v0s = buf;            // c*917 + i*131 + col
    float* v1s = buf + 3668;     // c*1960 + r*140 + e   (e < 138)

    const int bx  = blockIdx.x;          // 0..383
    const int t   = bx >> 7;             // / 128
    const int rem = bx & 127;
    const int n   = rem >> 1;
    const int h0  = rem & 1;
    const int x0  = 128 * h0 - 3;        // global col of local col 0
    const int qh  = n << 2;

    const int tid = threadIdx.x;
    const int xi  = tid >> 1;            // column item
    const int dh  = tid & 1;             // dy half: dy in {4dh-4 .. 4dh-1}
    const bool act = (tid < 262);        // 131*2 items

    const float* v0g = vid0 + (size_t)t * 32 * 65536;
    const float* v1g = vid1 + (size_t)t * 32 * 65536;

    float acc[4][8];
#pragma unroll
    for (int q = 0; q < 4; q++)
#pragma unroll
        for (int s1 = 0; s1 < 8; s1++) acc[q][s1] = 0.f;

    for (int c0 = 0; c0 < 32; c0 += 4) {
        __syncthreads();   // previous chunk fully consumed
        // ---- stage v0 chunk: rows refl(qh-3+i), cols refl(x0+col) ----
        for (int pos = tid; pos < 917; pos += THREADS) {
            int i   = pos / 131;
            int col = pos - i * 131;
            int hg  = refl(qh - 3 + i);
            int wg  = refl(x0 + col);
            const float* s = v0g + ((size_t)c0 << 16) + (hg << 8) + wg;
#pragma unroll
            for (int c = 0; c < 4; c++)
                v0s[c * V0_CS + pos] = s[c << 16];
        }
        // ---- stage v1 chunk: rows refl(qh-7+r), cols refl(x0-4+e) ----
        for (int pos = tid; pos < 14 * V1_W; pos += THREADS) {
            int r  = pos / V1_W;
            int e  = pos - r * V1_W;
            int hg = refl(qh - 7 + r);
            int wg = refl(x0 - 4 + e);
            const float* s = v1g + ((size_t)c0 << 16) + (hg << 8) + wg;
#pragma unroll
            for (int c = 0; c < 4; c++)
                v1s[c * V1_CS + r * V1_RS + e] = s[c << 16];
        }
        __syncthreads();

        // ---- compute: acc[q][s1] += a[i] * b[i+q], rows rr = i+q in 0..9 ----
        if (act) {
#pragma unroll
            for (int c = 0; c < 4; c++) {
                const float* va = v0s + c * V0_CS + xi;
                const float* vb = v1s + c * V1_CS + dh * (4 * V1_RS) + xi;
                float a[7];
#pragma unroll
                for (int i = 0; i < 7; i++) a[i] = va[i * V0_RS];
#pragma unroll
                for (int rr = 0; rr < 10; rr++) {
                    float bv[8];
#pragma unroll
                    for (int s1 = 0; s1 < 8; s1++) bv[s1] = vb[rr * V1_RS + s1];
#pragma unroll
                    for (int q = 0; q < 4; q++) {
                        int i = rr - q;
                        if (i >= 0 && i <= 6) {
#pragma unroll
                            for (int s1 = 0; s1 < 8; s1++)
                                acc[q][s1] = fmaf(a[i], bv[s1], acc[q][s1]);
                        }
                    }
                }
            }
        }
    }
    __syncthreads();

    // ---- flush colP: s = (4*dh+q)*8 + s1 ----
    float* colP  = buf;
    float* dists = buf + 8515;
    if (act) {
#pragma unroll
        for (int q = 0; q < 4; q++)
#pragma unroll
            for (int s1 = 0; s1 < 8; s1++)
                colP[xi * COLP_S + (4 * dh + q) * 8 + s1] = acc[q][s1];
    }
    __syncthreads();

    // ---- stage 2: dists[m][s] = sum_{j=0..6} colP[4m+j][s] ----
    for (int idx = tid; idx < 32 * 64; idx += THREADS) {
        int m = idx >> 6;
        int s = idx & 63;
        const float* cp = colP + (4 * m) * COLP_S + s;
        float d = cp[0];
#pragma unroll
        for (int j = 1; j < 7; j++) d += cp[j * COLP_S];
        dists[idx] = d;
    }
    __syncthreads();

    // ---- top-7: warps 0..7 handle 4 queries each ----
    const int w    = tid >> 5;
    const int lane = tid & 31;
    if (w < 8) {
        for (int mi = 0; mi < 4; mi++) {
            int m = w * 4 + mi;
            const float* sd = dists + m * 64;
            float a0 = sd[lane];
            float a1 = sd[lane + 32];
            if (lane == 4) a1 += 1e30f;   // self shift idx 36 boosted

            const int qm = h0 * 32 + m;
            const int qg = t * 4096 + n * 64 + qm;
            const int qw = qm << 2;
            float* dbase = out + (size_t)qg * 7;
            float* ibase = out + 86016 + (size_t)qg * 21;

#pragma unroll
            for (int k = 0; k < 7; k++) {
                float bv = (a0 >= a1) ? a0 : a1;
                int   bi = (a0 >= a1) ? lane : lane + 32;
#pragma unroll
                for (int o = 16; o > 0; o >>= 1) {
                    float ov = __shfl_xor_sync(0xffffffffu, bv, o);
                    int   oi = __shfl_xor_sync(0xffffffffu, bi, o);
                    if (ov > bv || (ov == bv && oi < bi)) { bv = ov; bi = oi; }
                }
                if (bi == lane)      a0 = -3.4e38f;
                if (bi == lane + 32) a1 = -3.4e38f;
                if (lane == 0) {
                    dbase[k] = sd[bi];
                    int s0 = bi >> 3;
                    int s1 = bi & 7;
                    ibase[k * 3 + 0] = (float)t;
                    ibase[k * 3 + 1] = (float)refl(qh + s0 - 4);
                    ibase[k * 3 + 2] = (float)refl(qw + s1 - 4);
                }
            }
        }
    }
}

extern "C" void kernel_launch(void* const* d_in, const int* in_sizes, int n_in,
                              void* d_out, int out_size)
{
    const float* vid0 = (const float*)d_in[0];
    const float* vid1 = (const float*)d_in[1];
    float* out = (float*)d_out;
    nls_kernel<<<384, THREADS>>>(vid0, vid1, out);
}